// round 12
// baseline (speedup 1.0000x reference)
#include <cuda_runtime.h>
#include <cuda_bf16.h>

// Lyapunov spectrum, map-reduce form (see R2/R3 derivation):
// row-GS norms of J(x,y,z)@Q equal those of J alone (Q orthonormal), so
//   lambda_k(b) = sum_t log(n_k(x_t,y_t,z_t)) / (T*DT)
// Row 0 norm is constant sqrt(0.82). Pythagorean GS-norm form:
//   s1 = |row1|^2 - d10^2
//   s2 = |row2|^2 - d20^2 - (w/|r1|)^2,  w = r1 . row2
//
// SINGLE fused kernel, grid (64 xg, 64 chunk), block 256 = 32 b4 x 8 t-lanes
// x 4 steps. Partials to scratch; the LAST chunk-block per x-group performs
// the cross-chunk reduction. Unlike R7, fences are executed by ONE thread
// per block (after bar.sync, which provides block-level happens-before), so
// the publication cost is ~one MEMBAR per block instead of 256.
// Final sums run in fixed chunk order in exactly one block -> deterministic.

#define T_STEPS 2048
#define BATCH   8192
#define B4      2048                 // BATCH/4
#define ROW4    2048                 // float4 per component row
#define STRIDE_T4 (3 * ROW4)         // 6144 float4 per time step
#define NCHUNK  64
#define NXGRP   64

__device__ float4 g_part1[NCHUNK][B4];
__device__ float4 g_part2[NCHUNK][B4];
__device__ int    g_counter[NXGRP];   // zero at load; self-resetting per launch

__device__ __forceinline__ float frsqrt_approx(float x) {
    float r; asm("rsqrt.approx.f32 %0, %1;" : "=f"(r) : "f"(x)); return r;
}
__device__ __forceinline__ float flog2_approx(float x) {
    float r; asm("lg2.approx.f32 %0, %1;" : "=f"(r) : "f"(x)); return r;
}

// Per-sample GS norms. Adds log2(s1) to l1, log2(s2) to l2.
__device__ __forceinline__ void gs_sample(float x, float y, float z,
                                          float& l1, float& l2)
{
    const float Q00 = 0.99388373f;     // 0.9 / sqrt(0.82)
    const float Q01 = 0.110431530f;    // 0.1 / sqrt(0.82)
    const float F22 = 0.97333334f;     // 1 - DT*8/3
    const float C99SQ = 0.9801f;       // 0.99^2
    const float F22SQ = 0.94737780f;   // F22^2

    const float a = fmaf(-0.01f, z, 0.28f);   // J10
    const float e = 0.01f * x;                // J21 (= -J12)
    const float d = 0.01f * y;                // J20

    // row1 = (a, 0.99, -e)
    const float d10 = fmaf(Q00, a, Q01 * 0.99f);
    float s1 = fmaf(a, a, C99SQ);
    s1 = fmaf(e, e, s1);
    s1 = fmaf(-d10, d10, s1);
    l1 += flog2_approx(s1);

    // r1 = row1 - d10*q0 (z-component = -e)
    const float r10 = fmaf(-d10, Q00, a);
    const float r11 = fmaf(-d10, Q01, 0.99f);

    // row2 = (d, e, F22)
    const float d20 = fmaf(Q00, d, Q01 * e);
    const float w   = fmaf(r10, d, fmaf(r11, e, -e * F22));
    const float inv1 = frsqrt_approx(s1);
    const float wi  = w * inv1;
    float s2 = fmaf(d, d, F22SQ);
    s2 = fmaf(e, e, s2);
    s2 = fmaf(-d20, d20, s2);
    s2 = fmaf(-wi, wi, s2);
    l2 += flog2_approx(s2);
}

__global__ void __launch_bounds__(256, 4)
lya_fused_kernel(const float4* __restrict__ traj4, float4* __restrict__ out4)
{
    const int bl = threadIdx.x & 31;
    const int tl = threadIdx.x >> 5;
    const int xg = blockIdx.x;
    const int b4 = (xg << 5) + bl;
    const int chunk = blockIdx.y;
    const int t0 = chunk * 32 + tl * 4;

    float4 acc1 = make_float4(0.f, 0.f, 0.f, 0.f);
    float4 acc2 = make_float4(0.f, 0.f, 0.f, 0.f);

    const float4* p = traj4 + (long)t0 * STRIDE_T4 + b4;

#pragma unroll
    for (int i = 0; i < 4; ++i) {
        const float4 xv = __ldcs(p);
        const float4 yv = __ldcs(p + ROW4);
        const float4 zv = __ldcs(p + 2 * ROW4);
        p += STRIDE_T4;

        gs_sample(xv.x, yv.x, zv.x, acc1.x, acc2.x);
        gs_sample(xv.y, yv.y, zv.y, acc1.y, acc2.y);
        gs_sample(xv.z, yv.z, zv.z, acc1.z, acc2.z);
        gs_sample(xv.w, yv.w, zv.w, acc1.w, acc2.w);
    }

    // ---- reduce over the 8 t-lanes, publish chunk partials ----
    __shared__ float4 red1[8][32];
    __shared__ float4 red2[8][32];
    red1[tl][bl] = acc1;
    red2[tl][bl] = acc2;
    __syncthreads();

    if (threadIdx.x < 64) {
        const int j = threadIdx.x & 31;
        const int bb = (xg << 5) + j;
        if (threadIdx.x < 32) {
            float4 s = red1[0][j];
#pragma unroll
            for (int k = 1; k < 8; ++k) {
                s.x += red1[k][j].x; s.y += red1[k][j].y;
                s.z += red1[k][j].z; s.w += red1[k][j].w;
            }
            g_part1[chunk][bb] = s;
        } else {
            float4 s = red2[0][j];
#pragma unroll
            for (int k = 1; k < 8; ++k) {
                s.x += red2[k][j].x; s.y += red2[k][j].y;
                s.z += red2[k][j].z; s.w += red2[k][j].w;
            }
            g_part2[chunk][bb] = s;
        }
    }

    // ---- last-arriver election: fence + atomic in ONE thread only ----
    // bar.sync gives block-level happens-before for the partial stores above;
    // tid0's fence then publishes them device-wide (documented CUDA pattern).
    __syncthreads();
    __shared__ int s_old;
    if (threadIdx.x == 0) {
        __threadfence();                       // release (this block's stores)
        s_old = atomicAdd(&g_counter[xg], 1);
    }
    __syncthreads();
    if (s_old != NCHUNK - 1) return;

    if (threadIdx.x == 0)
        __threadfence();                       // acquire (other blocks' stores)
    __syncthreads();                           // propagate acquire to block

    // ---- finisher: reduce 64 chunk partials for this xg's 32 b4 ----
    // threads = (32 b4-lanes bl, 8 chunk-lanes cl); each sums 8 chunks/row.
    const int cl = threadIdx.x >> 5;
    float4 a1 = make_float4(0.f, 0.f, 0.f, 0.f);
    float4 a2 = make_float4(0.f, 0.f, 0.f, 0.f);
#pragma unroll
    for (int i = 0; i < 8; ++i) {
        const int c = cl + (i << 3);
        const float4 v1 = __ldcg(&g_part1[c][b4]);
        const float4 v2 = __ldcg(&g_part2[c][b4]);
        a1.x += v1.x; a1.y += v1.y; a1.z += v1.z; a1.w += v1.w;
        a2.x += v2.x; a2.y += v2.y; a2.z += v2.z; a2.w += v2.w;
    }

    __syncthreads();            // reuse smem
    red1[cl][bl] = a1;
    red2[cl][bl] = a2;
    __syncthreads();

    const float C = 0.016922539f;     // 0.5*ln2 / 20.48
    if (threadIdx.x < 64) {
        const int j = threadIdx.x & 31;
        const int bb = (xg << 5) + j;
        if (threadIdx.x < 32) {
            float4 s = red1[0][j];
#pragma unroll
            for (int k = 1; k < 8; ++k) {
                s.x += red1[k][j].x; s.y += red1[k][j].y;
                s.z += red1[k][j].z; s.w += red1[k][j].w;
            }
            s.x *= C; s.y *= C; s.z *= C; s.w *= C;
            // constant row 0: 50*ln(0.82)
            out4[bb] = make_float4(-9.922547f, -9.922547f, -9.922547f, -9.922547f);
            out4[B4 + bb] = s;
        } else {
            float4 s = red2[0][j];
#pragma unroll
            for (int k = 1; k < 8; ++k) {
                s.x += red2[k][j].x; s.y += red2[k][j].y;
                s.z += red2[k][j].z; s.w += red2[k][j].w;
            }
            s.x *= C; s.y *= C; s.z *= C; s.w *= C;
            out4[2 * B4 + bb] = s;
        }
    }

    // reset counter for next graph replay (no further arrivals this launch)
    if (threadIdx.x == 0)
        g_counter[xg] = 0;
}

extern "C" void kernel_launch(void* const* d_in, const int* in_sizes, int n_in,
                              void* d_out, int out_size)
{
    const float4* traj4 = (const float4*)d_in[0];
    float4* out4 = (float4*)d_out;
    dim3 grid(NXGRP, NCHUNK);
    lya_fused_kernel<<<grid, 256>>>(traj4, out4);
}

// round 13
// speedup vs baseline: 1.0181x; 1.0181x over previous
#include <cuda_runtime.h>
#include <cuda_bf16.h>

// Lyapunov spectrum, map-reduce form (see R2/R3 derivation):
// row-GS norms of J(x,y,z)@Q equal those of J alone (Q orthonormal), so
//   lambda_k(b) = sum_t log(n_k(x_t,y_t,z_t)) / (T*DT)
// Row 0 norm is constant sqrt(0.82). Pythagorean GS-norm form:
//   s1 = |row1|^2 - d10^2
//   s2 = |row2|^2 - d20^2 - (w/|r1|)^2,  w = r1 . row2
//
// Stage 1: float4 over b; t in 64 chunks x 8 t-lanes x 4 steps; streaming
//          loads; 48-reg budget -> 5 blocks/SM (40 warps) for higher MLP.
// Stage 2: warp per b4, lane=chunk pair, coalesced L2-resident loads,
//          fixed-order shuffle butterfly -> bit-deterministic.

#define T_STEPS 2048
#define BATCH   8192
#define B4      2048                 // BATCH/4
#define ROW4    2048                 // float4 per component row
#define STRIDE_T4 (3 * ROW4)         // 6144 float4 per time step
#define NCHUNK  64

// [b4][row][chunk] : per-b4 contiguous 2*64*16B = 2KB
__device__ float4 g_part[B4][2][NCHUNK];

__device__ __forceinline__ float frsqrt_approx(float x) {
    float r; asm("rsqrt.approx.f32 %0, %1;" : "=f"(r) : "f"(x)); return r;
}
__device__ __forceinline__ float flog2_approx(float x) {
    float r; asm("lg2.approx.f32 %0, %1;" : "=f"(r) : "f"(x)); return r;
}

// Per-sample GS norms. Adds log2(s1) to l1, log2(s2) to l2.
__device__ __forceinline__ void gs_sample(float x, float y, float z,
                                          float& l1, float& l2)
{
    const float Q00 = 0.99388373f;     // 0.9 / sqrt(0.82)
    const float Q01 = 0.110431530f;    // 0.1 / sqrt(0.82)
    const float F22 = 0.97333334f;     // 1 - DT*8/3
    const float C99SQ = 0.9801f;       // 0.99^2
    const float F22SQ = 0.94737780f;   // F22^2

    const float a = fmaf(-0.01f, z, 0.28f);   // J10
    const float e = 0.01f * x;                // J21 (= -J12)
    const float d = 0.01f * y;                // J20

    // row1 = (a, 0.99, -e)
    const float d10 = fmaf(Q00, a, Q01 * 0.99f);
    float s1 = fmaf(a, a, C99SQ);
    s1 = fmaf(e, e, s1);
    s1 = fmaf(-d10, d10, s1);
    l1 += flog2_approx(s1);

    // r1 = row1 - d10*q0 (z-component = -e)
    const float r10 = fmaf(-d10, Q00, a);
    const float r11 = fmaf(-d10, Q01, 0.99f);

    // row2 = (d, e, F22)
    const float d20 = fmaf(Q00, d, Q01 * e);
    const float w   = fmaf(r10, d, fmaf(r11, e, -e * F22));
    const float inv1 = frsqrt_approx(s1);
    const float wi  = w * inv1;
    float s2 = fmaf(d, d, F22SQ);
    s2 = fmaf(e, e, s2);
    s2 = fmaf(-d20, d20, s2);
    s2 = fmaf(-wi, wi, s2);
    l2 += flog2_approx(s2);
}

// grid: (64, 64)  block: 256 = 32 b4-lanes x 8 t-lanes, 4 steps each.
// minBlocks=5 -> ~48-reg budget -> 40 resident warps/SM for deeper MLP.
__global__ void __launch_bounds__(256, 5)
lya_main_kernel(const float4* __restrict__ traj4)
{
    const int bl = threadIdx.x & 31;
    const int tl = threadIdx.x >> 5;
    const int b4 = (blockIdx.x << 5) + bl;
    const int chunk = blockIdx.y;
    const int t0 = chunk * 32 + tl * 4;

    float4 acc1 = make_float4(0.f, 0.f, 0.f, 0.f);
    float4 acc2 = make_float4(0.f, 0.f, 0.f, 0.f);

    const float4* p = traj4 + (long)t0 * STRIDE_T4 + b4;

#pragma unroll 2
    for (int i = 0; i < 4; ++i) {
        const float4 xv = __ldcs(p);
        const float4 yv = __ldcs(p + ROW4);
        const float4 zv = __ldcs(p + 2 * ROW4);
        p += STRIDE_T4;

        gs_sample(xv.x, yv.x, zv.x, acc1.x, acc2.x);
        gs_sample(xv.y, yv.y, zv.y, acc1.y, acc2.y);
        gs_sample(xv.z, yv.z, zv.z, acc1.z, acc2.z);
        gs_sample(xv.w, yv.w, zv.w, acc1.w, acc2.w);
    }

    // reduce over the 8 t-lanes
    __shared__ float4 red1[8][32];
    __shared__ float4 red2[8][32];
    red1[tl][bl] = acc1;
    red2[tl][bl] = acc2;
    __syncthreads();

    if (threadIdx.x < 64) {
        const int j = threadIdx.x & 31;
        const int bb = (blockIdx.x << 5) + j;
        if (threadIdx.x < 32) {
            float4 s = red1[0][j];
#pragma unroll
            for (int k = 1; k < 8; ++k) {
                s.x += red1[k][j].x; s.y += red1[k][j].y;
                s.z += red1[k][j].z; s.w += red1[k][j].w;
            }
            g_part[bb][0][chunk] = s;
        } else {
            float4 s = red2[0][j];
#pragma unroll
            for (int k = 1; k < 8; ++k) {
                s.x += red2[k][j].x; s.y += red2[k][j].y;
                s.z += red2[k][j].z; s.w += red2[k][j].w;
            }
            g_part[bb][1][chunk] = s;
        }
    }
}

// grid: 256 blocks x 256 threads; one warp per b4, lane covers 2 chunks.
__global__ void __launch_bounds__(256)
lya_reduce_kernel(float4* __restrict__ out4)
{
    const int lane = threadIdx.x & 31;
    const int b4   = (blockIdx.x << 3) + (threadIdx.x >> 5);

    const float4 u1 = g_part[b4][0][lane];
    const float4 w1 = g_part[b4][0][lane + 32];
    const float4 u2 = g_part[b4][1][lane];
    const float4 w2 = g_part[b4][1][lane + 32];

    float4 v1 = make_float4(u1.x + w1.x, u1.y + w1.y, u1.z + w1.z, u1.w + w1.w);
    float4 v2 = make_float4(u2.x + w2.x, u2.y + w2.y, u2.z + w2.z, u2.w + w2.w);

    // fixed-order butterfly over lanes (deterministic)
#pragma unroll
    for (int off = 16; off > 0; off >>= 1) {
        v1.x += __shfl_xor_sync(0xFFFFFFFFu, v1.x, off);
        v1.y += __shfl_xor_sync(0xFFFFFFFFu, v1.y, off);
        v1.z += __shfl_xor_sync(0xFFFFFFFFu, v1.z, off);
        v1.w += __shfl_xor_sync(0xFFFFFFFFu, v1.w, off);
        v2.x += __shfl_xor_sync(0xFFFFFFFFu, v2.x, off);
        v2.y += __shfl_xor_sync(0xFFFFFFFFu, v2.y, off);
        v2.z += __shfl_xor_sync(0xFFFFFFFFu, v2.z, off);
        v2.w += __shfl_xor_sync(0xFFFFFFFFu, v2.w, off);
    }

    if (lane == 0) {
        const float C = 0.016922539f;     // 0.5*ln2 / 20.48
        // constant row 0: 50*ln(0.82)
        out4[b4] = make_float4(-9.922547f, -9.922547f, -9.922547f, -9.922547f);
        out4[B4 + b4]     = make_float4(v1.x * C, v1.y * C, v1.z * C, v1.w * C);
        out4[2 * B4 + b4] = make_float4(v2.x * C, v2.y * C, v2.z * C, v2.w * C);
    }
}

extern "C" void kernel_launch(void* const* d_in, const int* in_sizes, int n_in,
                              void* d_out, int out_size)
{
    const float4* traj4 = (const float4*)d_in[0];
    float4* out4 = (float4*)d_out;
    dim3 grid(64, NCHUNK);
    lya_main_kernel<<<grid, 256>>>(traj4);
    lya_reduce_kernel<<<256, 256>>>(out4);
}

// round 14
// speedup vs baseline: 1.0623x; 1.0435x over previous
#include <cuda_runtime.h>
#include <cuda_bf16.h>

// Lyapunov spectrum, map-reduce form (see R2/R3 derivation):
// row-GS norms of J(x,y,z)@Q equal those of J alone (Q orthonormal), so
//   lambda_k(b) = sum_t log(n_k(x_t,y_t,z_t)) / (T*DT)
// Row 0 norm is constant sqrt(0.82) -> lambda_0 = 50*ln(0.82) for all b.
// Pythagorean GS-norm form:
//   s1 = |row1|^2 - d10^2
//   s2 = |row2|^2 - d20^2 - (w/|r1|)^2,  w = r1 . row2
//
// Best-measured configuration (R3..R13 sweep):
// Stage 1: grid (64,64), block 256 = 32 b4-lanes x 8 t-lanes x 4 steps,
//          __ldcs streaming loads, __launch_bounds__(256,4) [64 regs —
//          both 48-reg/hi-occ and 128-reg/lo-occ measured slower].
//          Chunk-0 blocks also emit the constant row-0 output.
// Stage 2: 256 blocks x 256 threads, warp per b4, lane = chunk pair,
//          coalesced L2-resident loads, fixed-order shuffle butterfly
//          (bit-deterministic). Plain launch — PDL and fusion both measured
//          slower than the bare launch floor.

#define T_STEPS 2048
#define BATCH   8192
#define B4      2048                 // BATCH/4
#define ROW4    2048                 // float4 per component row
#define STRIDE_T4 (3 * ROW4)         // 6144 float4 per time step
#define NCHUNK  64

// [b4][row][chunk] : per-b4 contiguous 2*64*16B = 2KB
__device__ float4 g_part[B4][2][NCHUNK];

__device__ __forceinline__ float frsqrt_approx(float x) {
    float r; asm("rsqrt.approx.f32 %0, %1;" : "=f"(r) : "f"(x)); return r;
}
__device__ __forceinline__ float flog2_approx(float x) {
    float r; asm("lg2.approx.f32 %0, %1;" : "=f"(r) : "f"(x)); return r;
}

// Per-sample GS norms. Adds log2(s1) to l1, log2(s2) to l2.
__device__ __forceinline__ void gs_sample(float x, float y, float z,
                                          float& l1, float& l2)
{
    const float Q00 = 0.99388373f;     // 0.9 / sqrt(0.82)
    const float Q01 = 0.110431530f;    // 0.1 / sqrt(0.82)
    const float F22 = 0.97333334f;     // 1 - DT*8/3
    const float C99SQ = 0.9801f;       // 0.99^2
    const float F22SQ = 0.94737780f;   // F22^2

    const float a = fmaf(-0.01f, z, 0.28f);   // J10
    const float e = 0.01f * x;                // J21 (= -J12)
    const float d = 0.01f * y;                // J20

    // row1 = (a, 0.99, -e)
    const float d10 = fmaf(Q00, a, Q01 * 0.99f);
    float s1 = fmaf(a, a, C99SQ);
    s1 = fmaf(e, e, s1);
    s1 = fmaf(-d10, d10, s1);
    l1 += flog2_approx(s1);

    // r1 = row1 - d10*q0 (z-component = -e)
    const float r10 = fmaf(-d10, Q00, a);
    const float r11 = fmaf(-d10, Q01, 0.99f);

    // row2 = (d, e, F22)
    const float d20 = fmaf(Q00, d, Q01 * e);
    const float w   = fmaf(r10, d, fmaf(r11, e, -e * F22));
    const float inv1 = frsqrt_approx(s1);
    const float wi  = w * inv1;
    float s2 = fmaf(d, d, F22SQ);
    s2 = fmaf(e, e, s2);
    s2 = fmaf(-d20, d20, s2);
    s2 = fmaf(-wi, wi, s2);
    l2 += flog2_approx(s2);
}

// grid: (64, 64)  block: 256 = 32 b4-lanes x 8 t-lanes, 4 steps each
__global__ void __launch_bounds__(256, 4)
lya_main_kernel(const float4* __restrict__ traj4, float4* __restrict__ out4)
{
    const int bl = threadIdx.x & 31;
    const int tl = threadIdx.x >> 5;
    const int b4 = (blockIdx.x << 5) + bl;
    const int chunk = blockIdx.y;
    const int t0 = chunk * 32 + tl * 4;

    float4 acc1 = make_float4(0.f, 0.f, 0.f, 0.f);
    float4 acc2 = make_float4(0.f, 0.f, 0.f, 0.f);

    const float4* p = traj4 + (long)t0 * STRIDE_T4 + b4;

#pragma unroll
    for (int i = 0; i < 4; ++i) {
        const float4 xv = __ldcs(p);
        const float4 yv = __ldcs(p + ROW4);
        const float4 zv = __ldcs(p + 2 * ROW4);
        p += STRIDE_T4;

        gs_sample(xv.x, yv.x, zv.x, acc1.x, acc2.x);
        gs_sample(xv.y, yv.y, zv.y, acc1.y, acc2.y);
        gs_sample(xv.z, yv.z, zv.z, acc1.z, acc2.z);
        gs_sample(xv.w, yv.w, zv.w, acc1.w, acc2.w);
    }

    // reduce over the 8 t-lanes
    __shared__ float4 red1[8][32];
    __shared__ float4 red2[8][32];
    red1[tl][bl] = acc1;
    red2[tl][bl] = acc2;
    __syncthreads();

    if (threadIdx.x < 64) {
        const int j = threadIdx.x & 31;
        const int bb = (blockIdx.x << 5) + j;
        if (threadIdx.x < 32) {
            float4 s = red1[0][j];
#pragma unroll
            for (int k = 1; k < 8; ++k) {
                s.x += red1[k][j].x; s.y += red1[k][j].y;
                s.z += red1[k][j].z; s.w += red1[k][j].w;
            }
            g_part[bb][0][chunk] = s;
            // chunk-0 blocks emit the constant row-0 output (free slot here)
            if (chunk == 0)
                out4[bb] = make_float4(-9.922547f, -9.922547f,
                                       -9.922547f, -9.922547f);
        } else {
            float4 s = red2[0][j];
#pragma unroll
            for (int k = 1; k < 8; ++k) {
                s.x += red2[k][j].x; s.y += red2[k][j].y;
                s.z += red2[k][j].z; s.w += red2[k][j].w;
            }
            g_part[bb][1][chunk] = s;
        }
    }
}

// grid: 256 blocks x 256 threads; one warp per b4, lane covers 2 chunks.
__global__ void __launch_bounds__(256)
lya_reduce_kernel(float4* __restrict__ out4)
{
    const int lane = threadIdx.x & 31;
    const int b4   = (blockIdx.x << 3) + (threadIdx.x >> 5);

    const float4 u1 = g_part[b4][0][lane];
    const float4 w1 = g_part[b4][0][lane + 32];
    const float4 u2 = g_part[b4][1][lane];
    const float4 w2 = g_part[b4][1][lane + 32];

    float4 v1 = make_float4(u1.x + w1.x, u1.y + w1.y, u1.z + w1.z, u1.w + w1.w);
    float4 v2 = make_float4(u2.x + w2.x, u2.y + w2.y, u2.z + w2.z, u2.w + w2.w);

    // fixed-order butterfly over lanes (deterministic)
#pragma unroll
    for (int off = 16; off > 0; off >>= 1) {
        v1.x += __shfl_xor_sync(0xFFFFFFFFu, v1.x, off);
        v1.y += __shfl_xor_sync(0xFFFFFFFFu, v1.y, off);
        v1.z += __shfl_xor_sync(0xFFFFFFFFu, v1.z, off);
        v1.w += __shfl_xor_sync(0xFFFFFFFFu, v1.w, off);
        v2.x += __shfl_xor_sync(0xFFFFFFFFu, v2.x, off);
        v2.y += __shfl_xor_sync(0xFFFFFFFFu, v2.y, off);
        v2.z += __shfl_xor_sync(0xFFFFFFFFu, v2.z, off);
        v2.w += __shfl_xor_sync(0xFFFFFFFFu, v2.w, off);
    }

    if (lane == 0) {
        const float C = 0.016922539f;     // 0.5*ln2 / 20.48
        out4[B4 + b4]     = make_float4(v1.x * C, v1.y * C, v1.z * C, v1.w * C);
        out4[2 * B4 + b4] = make_float4(v2.x * C, v2.y * C, v2.z * C, v2.w * C);
    }
}

extern "C" void kernel_launch(void* const* d_in, const int* in_sizes, int n_in,
                              void* d_out, int out_size)
{
    const float4* traj4 = (const float4*)d_in[0];
    float4* out4 = (float4*)d_out;
    dim3 grid(64, NCHUNK);
    lya_main_kernel<<<grid, 256>>>(traj4, out4);
    lya_reduce_kernel<<<256, 256>>>(out4);
}